// round 2
// baseline (speedup 1.0000x reference)
#include <cuda_runtime.h>
#include <math.h>
#include <stdint.h>

// ---------------- problem dims ----------------
#define NB 32      // batch B
#define NC 512     // C
#define NT 1024    // N tokens
#define NE 512     // E
#define ND 2048    // D
#define NH 8       // heads
#define HD 64      // head dim
#define NSTEP 50   // T
#define NOUT 1000  // O
#define NA_ 512    // NA
#define NO_ 512    // NO

// output layout offsets (outputs flattened & concatenated in return order)
#define PRED_ELEMS (NB*NOUT*NSTEP)        // 1,600,000
#define CERT_BASE  PRED_ELEMS
#define CERT_ELEMS (NB*2*NSTEP)           // 3,200
#define SYNC_BASE  (CERT_BASE + CERT_ELEMS) // 1,603,200

// ---------------- device scratch (no allocs allowed) ----------------
__device__ float buf_feats[NB*NT*NC];  // 64MB
__device__ float buf_kv   [NB*NT*NE];  // 64MB
__device__ float buf_K    [NB*NT*NE];  // 64MB
__device__ float buf_V    [NB*NT*NE];  // 64MB

__device__ float buf_act  [NB*ND];
__device__ float buf_aA   [NB*NA_];
__device__ float buf_bA   [NB*NA_];
__device__ float buf_syncA[NB*NA_];
__device__ float buf_aO   [NB*NO_];
__device__ float buf_bO   [NB*NO_];
__device__ float buf_syncO[NB*NO_];
__device__ float buf_qh   [NB*NE];
__device__ float buf_attn [NB*NE];
__device__ float buf_attno[NB*NE];
__device__ float buf_h    [NB*2*ND];
__device__ float buf_hpm  [NB*ND];
__device__ float buf_t1   [NB*ND];
__device__ float buf_pred [NB*NOUT];
__device__ float buf_Wqq  [NE*NE];
__device__ float buf_bqq  [NE];

// ---------------- block reductions ----------------
__device__ __forceinline__ float blockReduceSum(float v) {
    __shared__ float shs[32];
    int lane = threadIdx.x & 31, w = threadIdx.x >> 5;
    #pragma unroll
    for (int o = 16; o; o >>= 1) v += __shfl_xor_sync(0xffffffffu, v, o);
    if (lane == 0) shs[w] = v;
    __syncthreads();
    float r = 0.f;
    int nw = (blockDim.x + 31) >> 5;
    if (threadIdx.x < nw) r = shs[threadIdx.x];
    if (w == 0) {
        #pragma unroll
        for (int o = 16; o; o >>= 1) r += __shfl_xor_sync(0xffffffffu, r, o);
        if (lane == 0) shs[0] = r;
    }
    __syncthreads();
    float out = shs[0];
    __syncthreads();
    return out;
}

__device__ __forceinline__ float blockReduceMax(float v) {
    __shared__ float shm[32];
    int lane = threadIdx.x & 31, w = threadIdx.x >> 5;
    #pragma unroll
    for (int o = 16; o; o >>= 1) v = fmaxf(v, __shfl_xor_sync(0xffffffffu, v, o));
    if (lane == 0) shm[w] = v;
    __syncthreads();
    float r = -1e30f;
    int nw = (blockDim.x + 31) >> 5;
    if (threadIdx.x < nw) r = shm[threadIdx.x];
    if (w == 0) {
        #pragma unroll
        for (int o = 16; o; o >>= 1) r = fmaxf(r, __shfl_xor_sync(0xffffffffu, r, o));
        if (lane == 0) shm[0] = r;
    }
    __syncthreads();
    float out = shm[0];
    __syncthreads();
    return out;
}

// ---------------- transpose x (B,C,N) -> feats (B,N,C) ----------------
__global__ void transpose_x(const float* __restrict__ x) {
    __shared__ float tile[32][33];
    int b = blockIdx.z;
    int n0 = blockIdx.x * 32, c0 = blockIdx.y * 32;
    int tx = threadIdx.x, ty = threadIdx.y; // (32,8)
    const float* xp = x + (size_t)b * NC * NT;
    #pragma unroll
    for (int i = 0; i < 4; i++) {
        int c = c0 + ty + i * 8;
        tile[ty + i * 8][tx] = xp[(size_t)c * NT + n0 + tx];
    }
    __syncthreads();
    float* fp = buf_feats + (size_t)b * NT * NC;
    #pragma unroll
    for (int i = 0; i < 4; i++) {
        int n = n0 + ty + i * 8;
        fp[(size_t)n * NC + c0 + tx] = tile[tx][ty + i * 8];
    }
}

// ---------------- big fp32 GEMM: C[M,N] = A@B + bias ----------------
// BM=128, BN=64, BK=16, 256 threads, 8x4 micro-tile. M%128==0, N%64==0, K%16==0.
__global__ void gemm_f32(const float* __restrict__ A, int lda,
                         const float* __restrict__ B, int ldb,
                         const float* __restrict__ bias,
                         float* __restrict__ C, int ldc, int K) {
    __shared__ float As[16][128 + 4];
    __shared__ float Bs[16][64];
    const int tid = threadIdx.x;
    const int tx = tid & 15;
    const int ty = tid >> 4;
    const int row0 = blockIdx.y * 128;
    const int col0 = blockIdx.x * 64;
    float acc[8][4];
    #pragma unroll
    for (int i = 0; i < 8; i++)
        #pragma unroll
        for (int j = 0; j < 4; j++) acc[i][j] = 0.f;

    for (int k0 = 0; k0 < K; k0 += 16) {
        #pragma unroll
        for (int i = 0; i < 8; i++) {
            int e = tid + i * 256;
            int r = e >> 4, kk = e & 15;
            As[kk][r] = A[(size_t)(row0 + r) * lda + k0 + kk];
        }
        #pragma unroll
        for (int i = 0; i < 4; i++) {
            int e = tid + i * 256;
            int kk = e >> 6, n = e & 63;
            Bs[kk][n] = B[(size_t)(k0 + kk) * ldb + col0 + n];
        }
        __syncthreads();
        #pragma unroll
        for (int kk = 0; kk < 16; kk++) {
            float a[8], bb[4];
            #pragma unroll
            for (int i = 0; i < 8; i++) a[i] = As[kk][ty * 8 + i];
            #pragma unroll
            for (int j = 0; j < 4; j++) bb[j] = Bs[kk][tx * 4 + j];
            #pragma unroll
            for (int i = 0; i < 8; i++)
                #pragma unroll
                for (int j = 0; j < 4; j++)
                    acc[i][j] += a[i] * bb[j];
        }
        __syncthreads();
    }
    #pragma unroll
    for (int i = 0; i < 8; i++) {
        int r = row0 + ty * 8 + i;
        #pragma unroll
        for (int j = 0; j < 4; j++) {
            int c = col0 + tx * 4 + j;
            C[(size_t)r * ldc + c] = acc[i][j] + (bias ? bias[c] : 0.f);
        }
    }
}

// ---------------- row LayerNorm (in place) ----------------
__global__ void ln_rows(float* __restrict__ X, int L,
                        const float* __restrict__ g, const float* __restrict__ b) {
    int row = blockIdx.x;
    float* xp = X + (size_t)row * L;
    float s = 0.f;
    for (int i = threadIdx.x; i < L; i += blockDim.x) s += xp[i];
    s = blockReduceSum(s);
    float m = s / L;
    float v = 0.f;
    for (int i = threadIdx.x; i < L; i += blockDim.x) { float d = xp[i] - m; v += d * d; }
    v = blockReduceSum(v);
    float inv = rsqrtf(v / L + 1e-5f);
    for (int i = threadIdx.x; i < L; i += blockDim.x)
        xp[i] = (xp[i] - m) * inv * g[i] + b[i];
}

// ---------------- fused bias: bqq = b_q @ Wq_a + bq_a ----------------
__global__ void make_bqq(const float* __restrict__ b_q, const float* __restrict__ W_in,
                         const float* __restrict__ b_in) {
    int j = blockIdx.x * blockDim.x + threadIdx.x;
    if (j >= NE) return;
    float s = b_in[j];
    for (int k = 0; k < NE; k++) s += b_q[k] * W_in[(size_t)k * (3 * NE) + j];
    buf_bqq[j] = s;
}

// ---------------- state init ----------------
__global__ void init_state(const float* __restrict__ start) {
    int i = blockIdx.x * blockDim.x + threadIdx.x;
    if (i < NB * ND) buf_act[i] = start[i & (ND - 1)];
    if (i < NB * NA_) { buf_aA[i] = 0.f; buf_bA[i] = 0.f; buf_aO[i] = 0.f; buf_bO[i] = 0.f; }
}

// ---------------- syncA update ----------------
__global__ void syncA_update(const int* __restrict__ idx, const float* __restrict__ decay) {
    int b = blockIdx.x, i = threadIdx.x;
    float r = expf(-fminf(fmaxf(decay[i], 0.f), 15.f));
    float sel = buf_act[b * ND + idx[i]];
    float a = r * buf_aA[b * NA_ + i] + sel * sel;
    float bb = r * buf_bA[b * NA_ + i] + 1.f;
    buf_aA[b * NA_ + i] = a;
    buf_bA[b * NA_ + i] = bb;
    buf_syncA[b * NA_ + i] = a * rsqrtf(bb);
}

// ---------------- syncO update (+ final sync output) ----------------
__global__ void syncO_update(const int* __restrict__ idx, const float* __restrict__ decay,
                             float* __restrict__ dout, int t) {
    int b = blockIdx.x, i = threadIdx.x;
    float r = expf(-fminf(fmaxf(decay[i], 0.f), 15.f));
    float sel = buf_act[b * ND + idx[i]];
    float a = r * buf_aO[b * NO_ + i] + sel * sel;
    float bb = r * buf_bO[b * NO_ + i] + 1.f;
    buf_aO[b * NO_ + i] = a;
    buf_bO[b * NO_ + i] = bb;
    float sy = a * rsqrtf(bb);
    buf_syncO[b * NO_ + i] = sy;
    if (t == NSTEP - 1) dout[SYNC_BASE + b * NO_ + i] = sy;
}

// ---------------- skinny GEMM: M=32, concat A supported ----------------
// C[32, Nout] = [A0 | A1] @ B + bias, optional ReLU. BN=32, BK=16, 256 thr.
__global__ void skinny32(const float* __restrict__ A0, int K0,
                         const float* __restrict__ A1, int K1,
                         const float* __restrict__ B, int ldb,
                         const float* __restrict__ bias,
                         float* __restrict__ C, int Nout, int relu) {
    __shared__ float As[16][33];
    const int lane = threadIdx.x & 31;
    const int wg = threadIdx.x >> 5; // 8 warps -> rows wg*4..wg*4+3
    const int col = blockIdx.x * 32 + lane;
    const int Kt = K0 + K1;
    float acc0 = 0.f, acc1 = 0.f, acc2 = 0.f, acc3 = 0.f;

    for (int k0 = 0; k0 < Kt; k0 += 16) {
        #pragma unroll
        for (int i = 0; i < 2; i++) {
            int e = threadIdx.x + i * 256;
            int r = e >> 4, kk = e & 15;
            int k = k0 + kk;
            As[kk][r] = (k < K0) ? A0[r * K0 + k] : A1[r * K1 + (k - K0)];
        }
        __syncthreads();
        if (col < Nout) {
            float bv[16];
            #pragma unroll
            for (int kk = 0; kk < 16; kk++)
                bv[kk] = B[(size_t)(k0 + kk) * ldb + col];
            int r0 = wg * 4;
            #pragma unroll
            for (int kk = 0; kk < 16; kk++) {
                acc0 += As[kk][r0 + 0] * bv[kk];
                acc1 += As[kk][r0 + 1] * bv[kk];
                acc2 += As[kk][r0 + 2] * bv[kk];
                acc3 += As[kk][r0 + 3] * bv[kk];
            }
        }
        __syncthreads();
    }
    if (col < Nout) {
        float bb = bias ? bias[col] : 0.f;
        float o0 = acc0 + bb, o1 = acc1 + bb, o2 = acc2 + bb, o3 = acc3 + bb;
        if (relu) {
            o0 = fmaxf(o0, 0.f); o1 = fmaxf(o1, 0.f);
            o2 = fmaxf(o2, 0.f); o3 = fmaxf(o3, 0.f);
        }
        int r0 = wg * 4;
        C[(size_t)(r0 + 0) * Nout + col] = o0;
        C[(size_t)(r0 + 1) * Nout + col] = o1;
        C[(size_t)(r0 + 2) * Nout + col] = o2;
        C[(size_t)(r0 + 3) * Nout + col] = o3;
    }
}

// ---------------- decode attention: one block per (b,h) ----------------
__global__ void attn_kernel() {
    const int bh = blockIdx.x;
    const int b = bh >> 3, h = bh & 7;
    const int tid = threadIdx.x;
    __shared__ float qs[64];
    __shared__ float sc[NT];
    __shared__ float red[256];
    if (tid < 64) qs[tid] = buf_qh[b * NE + h * HD + tid];
    __syncthreads();

    // pass 1: scores
    const int lane = tid & 31, w = tid >> 5;
    for (int n = w; n < NT; n += 8) {
        const float* kp = buf_K + (size_t)(b * NT + n) * NE + h * HD;
        float p = qs[lane] * kp[lane] + qs[lane + 32] * kp[lane + 32];
        #pragma unroll
        for (int o = 16; o; o >>= 1) p += __shfl_xor_sync(0xffffffffu, p, o);
        if (lane == 0) sc[n] = p * 0.125f; // 1/sqrt(64)
    }
    __syncthreads();

    // softmax
    float m = -1e30f;
    for (int i = tid; i < NT; i += 256) m = fmaxf(m, sc[i]);
    m = blockReduceMax(m);
    float s = 0.f;
    for (int i = tid; i < NT; i += 256) { float e = expf(sc[i] - m); sc[i] = e; s += e; }
    s = blockReduceSum(s);
    float inv = 1.f / s;

    // pass 2: attn = w @ V
    const int d = tid & 63, chunk = tid >> 6;
    float acc = 0.f;
    const float* vp = buf_V + (size_t)(b * NT) * NE + h * HD + d;
    #pragma unroll 8
    for (int n = chunk * 256; n < chunk * 256 + 256; n++)
        acc += sc[n] * vp[(size_t)n * NE];
    red[tid] = acc;
    __syncthreads();
    if (tid < 64) {
        float sum = red[tid] + red[tid + 64] + red[tid + 128] + red[tid + 192];
        buf_attn[b * NE + h * HD + tid] = sum * inv;
    }
}

// ---------------- fused GLU + double LayerNorm ----------------
__global__ void glu_ln_ln(const float* __restrict__ g_syn, const float* __restrict__ be_syn,
                          const float* __restrict__ g_pm, const float* __restrict__ be_pm) {
    int b = blockIdx.x, tid = threadIdx.x;
    const float* hp = buf_h + (size_t)b * 2 * ND;
    float v[8];
    #pragma unroll
    for (int j = 0; j < 8; j++) {
        int d = tid + j * 256;
        float a = hp[d], gg = hp[ND + d];
        v[j] = a * (1.f / (1.f + expf(-gg)));
    }
    float s = 0.f;
    #pragma unroll
    for (int j = 0; j < 8; j++) s += v[j];
    s = blockReduceSum(s);
    float m = s / ND;
    float var = 0.f;
    #pragma unroll
    for (int j = 0; j < 8; j++) { float d = v[j] - m; var += d * d; }
    var = blockReduceSum(var);
    float inv = rsqrtf(var / ND + 1e-5f);
    #pragma unroll
    for (int j = 0; j < 8; j++) {
        int d = tid + j * 256;
        v[j] = (v[j] - m) * inv * g_syn[d] + be_syn[d];
    }
    // second LN
    s = 0.f;
    #pragma unroll
    for (int j = 0; j < 8; j++) s += v[j];
    s = blockReduceSum(s);
    float m2 = s / ND;
    var = 0.f;
    #pragma unroll
    for (int j = 0; j < 8; j++) { float d = v[j] - m2; var += d * d; }
    var = blockReduceSum(var);
    float inv2 = rsqrtf(var / ND + 1e-5f);
    #pragma unroll
    for (int j = 0; j < 8; j++) {
        int d = tid + j * 256;
        buf_hpm[(size_t)b * ND + d] = (v[j] - m2) * inv2 * g_pm[d] + be_pm[d];
    }
}

// ---------------- entropy + prediction write ----------------
__global__ void entropy_write(float* __restrict__ dout, int t) {
    int b = blockIdx.x, tid = threadIdx.x;
    const float* p = buf_pred + (size_t)b * NOUT;
    float m = -1e30f;
    for (int i = tid; i < NOUT; i += 256) m = fmaxf(m, p[i]);
    m = blockReduceMax(m);
    float s = 0.f;
    for (int i = tid; i < NOUT; i += 256) s += expf(p[i] - m);
    s = blockReduceSum(s);
    float lse = m + logf(s);
    float ent = 0.f;
    for (int i = tid; i < NOUT; i += 256) {
        float pv = p[i];
        float lp = pv - lse;
        ent += expf(lp) * lp;
        dout[(size_t)b * NOUT * NSTEP + (size_t)i * NSTEP + t] = pv;
    }
    ent = blockReduceSum(ent);
    if (tid == 0) {
        float ne = -ent / logf((float)NOUT);
        dout[CERT_BASE + b * (2 * NSTEP) + 0 * NSTEP + t] = ne;
        dout[CERT_BASE + b * (2 * NSTEP) + 1 * NSTEP + t] = 1.f - ne;
    }
}

// ---------------- launch ----------------
extern "C" void kernel_launch(void* const* d_in, const int* in_sizes, int n_in,
                              void* d_out, int out_size) {
    const float* x     = (const float*)d_in[0];
    const float* W_kv  = (const float*)d_in[1];
    const float* b_kv  = (const float*)d_in[2];
    const float* g_kv  = (const float*)d_in[3];
    const float* be_kv = (const float*)d_in[4];
    const float* W_q   = (const float*)d_in[5];
    const float* b_q   = (const float*)d_in[6];
    const float* W_in  = (const float*)d_in[7];
    const float* b_in  = (const float*)d_in[8];
    const float* W_ao  = (const float*)d_in[9];
    const float* b_ao  = (const float*)d_in[10];
    const float* W_syn = (const float*)d_in[11];
    const float* b_syn = (const float*)d_in[12];
    const float* g_syn = (const float*)d_in[13];
    const float* be_syn= (const float*)d_in[14];
    const float* g_pm  = (const float*)d_in[15];
    const float* be_pm = (const float*)d_in[16];
    const float* W1    = (const float*)d_in[17];
    const float* b1    = (const float*)d_in[18];
    const float* W2    = (const float*)d_in[19];
    const float* b2    = (const float*)d_in[20];
    const float* start = (const float*)d_in[21];
    const float* dec_a = (const float*)d_in[22];
    const float* dec_o = (const float*)d_in[23];
    const float* W_out = (const float*)d_in[24];
    const float* b_out = (const float*)d_in[25];
    const int*   idx_a = (const int*)d_in[26];
    const int*   idx_o = (const int*)d_in[27];
    float* out = (float*)d_out;

    float *p_feats, *p_kv, *p_K, *p_V, *p_Wqq, *p_bqq;
    float *p_syncA, *p_qh, *p_attn, *p_attno, *p_act, *p_h, *p_hpm, *p_t1, *p_syncO, *p_pred;
    cudaGetSymbolAddress((void**)&p_feats, buf_feats);
    cudaGetSymbolAddress((void**)&p_kv,    buf_kv);
    cudaGetSymbolAddress((void**)&p_K,     buf_K);
    cudaGetSymbolAddress((void**)&p_V,     buf_V);
    cudaGetSymbolAddress((void**)&p_Wqq,   buf_Wqq);
    cudaGetSymbolAddress((void**)&p_bqq,   buf_bqq);
    cudaGetSymbolAddress((void**)&p_syncA, buf_syncA);
    cudaGetSymbolAddress((void**)&p_qh,    buf_qh);
    cudaGetSymbolAddress((void**)&p_attn,  buf_attn);
    cudaGetSymbolAddress((void**)&p_attno, buf_attno);
    cudaGetSymbolAddress((void**)&p_act,   buf_act);
    cudaGetSymbolAddress((void**)&p_h,     buf_h);
    cudaGetSymbolAddress((void**)&p_hpm,   buf_hpm);
    cudaGetSymbolAddress((void**)&p_t1,    buf_t1);
    cudaGetSymbolAddress((void**)&p_syncO, buf_syncO);
    cudaGetSymbolAddress((void**)&p_pred,  buf_pred);

    // ---- precompute ----
    transpose_x<<<dim3(NT / 32, NC / 32, NB), dim3(32, 8)>>>(x);
    // kv = LN(feats @ W_kv + b_kv)
    gemm_f32<<<dim3(NE / 64, (NB * NT) / 128), 256>>>(p_feats, NC, W_kv, NE, b_kv, p_kv, NE, NC);
    ln_rows<<<NB * NT, 256>>>(p_kv, NE, g_kv, be_kv);
    // K = kv @ Wk_a + bk ; V = kv @ Wv_a + bv   (column blocks of W_in, ld = 3E)
    gemm_f32<<<dim3(NE / 64, (NB * NT) / 128), 256>>>(p_kv, NE, W_in + NE,     3 * NE, b_in + NE,     p_K, NE, NE);
    gemm_f32<<<dim3(NE / 64, (NB * NT) / 128), 256>>>(p_kv, NE, W_in + 2 * NE, 3 * NE, b_in + 2 * NE, p_V, NE, NE);
    // W_qq = W_q @ Wq_a (fold two affine maps), b_qq = b_q @ Wq_a + bq_a
    gemm_f32<<<dim3(NE / 64, NE / 128), 256>>>(W_q, NE, W_in, 3 * NE, (const float*)0, p_Wqq, NE, NE);
    make_bqq<<<2, 256>>>(b_q, W_in, b_in);
    init_state<<<(NB * ND + 255) / 256, 256>>>(start);

    // ---- recurrent loop ----
    for (int t = 0; t < NSTEP; t++) {
        syncA_update<<<NB, NA_>>>(idx_a, dec_a);
        // qh = syncA @ W_qq + b_qq
        skinny32<<<NE / 32, 256>>>(p_syncA, NA_, (const float*)0, 0, p_Wqq, NE, p_bqq, p_qh, NE, 0);
        attn_kernel<<<NB * NH, 256>>>();
        // attn_o = attn @ W_ao + b_ao
        skinny32<<<NE / 32, 256>>>(p_attn, NE, (const float*)0, 0, W_ao, NE, b_ao, p_attno, NE, 0);
        // h = [attn_o | act] @ W_syn + b_syn
        skinny32<<<(2 * ND) / 32, 256>>>(p_attno, NE, p_act, ND, W_syn, 2 * ND, b_syn, p_h, 2 * ND, 0);
        glu_ln_ln<<<NB, 256>>>(g_syn, be_syn, g_pm, be_pm);
        // act = relu(relu(hpm@W1+b1)@W2+b2)
        skinny32<<<ND / 32, 256>>>(p_hpm, ND, (const float*)0, 0, W1, ND, b1, p_t1, ND, 1);
        skinny32<<<ND / 32, 256>>>(p_t1, ND, (const float*)0, 0, W2, ND, b2, p_act, ND, 1);
        syncO_update<<<NB, NO_>>>(idx_o, dec_o, out, t);
        // pred = syncO @ W_out + b_out
        skinny32<<<(NOUT + 31) / 32, 256>>>(p_syncO, NO_, (const float*)0, 0, W_out, NOUT, b_out, p_pred, NOUT, 0);
        entropy_write<<<NB, 256>>>(out, t);
    }
}

// round 3
// speedup vs baseline: 7.0746x; 7.0746x over previous
#include <cuda_runtime.h>
#include <math.h>
#include <stdint.h>

// ---------------- problem dims ----------------
#define NB 32
#define NC 512
#define NT 1024
#define NE 512
#define ND 2048
#define NH 8
#define HD 64
#define NSTEP 50
#define NOUT 1000
#define NA_ 512
#define NO_ 512

#define PRED_ELEMS (NB*NOUT*NSTEP)
#define CERT_BASE  PRED_ELEMS
#define SYNC_BASE  (CERT_BASE + NB*2*NSTEP)

// ---------------- device scratch ----------------
__device__ float buf_feats[NB*NT*NC];
__device__ float buf_kv   [NB*NT*NE];
__device__ float buf_K    [NB*NT*NE];   // head-major: [b][h][n][d]
__device__ float buf_V    [NB*NT*NE];   // head-major
__device__ float buf_act  [NB*ND];
__device__ float buf_aA   [NB*NA_];
__device__ float buf_bA   [NB*NA_];
__device__ float buf_syncA[NB*NA_];
__device__ float buf_aO   [NB*NO_];
__device__ float buf_bO   [NB*NO_];
__device__ float buf_syncO[NB*NO_];
__device__ float buf_attn [NB*NE];
__device__ float buf_attno[NB*NE];
__device__ float buf_hpm  [NB*ND];
__device__ float buf_t1   [NB*ND];
__device__ float buf_Wqq  [NE*NE];
__device__ float buf_bqq  [NE];
// split-K partials
__device__ float buf_qpart    [8*32*NE];
__device__ float buf_attnopart[4*32*NE];
__device__ float buf_hpart    [8*32*2*ND];
__device__ float buf_w1part   [4*32*ND];
__device__ float buf_w2part   [4*32*ND];
__device__ float buf_predpart [2*32*NOUT];
// attention partials
__device__ float buf_pv[NB*NH*8*HD];
__device__ float buf_pm[NB*NH*8];
__device__ float buf_ps[NB*NH*8];

// ---------------- cp.async helpers ----------------
__device__ __forceinline__ void cp16(void* smem, const void* gmem) {
    uint32_t s = (uint32_t)__cvta_generic_to_shared(smem);
    asm volatile("cp.async.cg.shared.global [%0], [%1], 16;\n" :: "r"(s), "l"(gmem));
}
#define CP_COMMIT() asm volatile("cp.async.commit_group;\n" ::: "memory")
#define CP_WAIT2()  asm volatile("cp.async.wait_group 2;\n" ::: "memory")

// ---------------- block reductions ----------------
__device__ __forceinline__ float blockReduceSum(float v) {
    __shared__ float shs[32];
    int lane = threadIdx.x & 31, w = threadIdx.x >> 5;
    #pragma unroll
    for (int o = 16; o; o >>= 1) v += __shfl_xor_sync(0xffffffffu, v, o);
    if (lane == 0) shs[w] = v;
    __syncthreads();
    float r = 0.f;
    int nw = (blockDim.x + 31) >> 5;
    if (threadIdx.x < nw) r = shs[threadIdx.x];
    if (w == 0) {
        #pragma unroll
        for (int o = 16; o; o >>= 1) r += __shfl_xor_sync(0xffffffffu, r, o);
        if (lane == 0) shs[0] = r;
    }
    __syncthreads();
    float out = shs[0];
    __syncthreads();
    return out;
}
__device__ __forceinline__ float blockReduceMax(float v) {
    __shared__ float shm[32];
    int lane = threadIdx.x & 31, w = threadIdx.x >> 5;
    #pragma unroll
    for (int o = 16; o; o >>= 1) v = fmaxf(v, __shfl_xor_sync(0xffffffffu, v, o));
    if (lane == 0) shm[w] = v;
    __syncthreads();
    float r = -1e30f;
    int nw = (blockDim.x + 31) >> 5;
    if (threadIdx.x < nw) r = shm[threadIdx.x];
    if (w == 0) {
        #pragma unroll
        for (int o = 16; o; o >>= 1) r = fmaxf(r, __shfl_xor_sync(0xffffffffu, r, o));
        if (lane == 0) shm[0] = r;
    }
    __syncthreads();
    float out = shm[0];
    __syncthreads();
    return out;
}

// ---------------- transpose ----------------
__global__ void transpose_x(const float* __restrict__ x) {
    __shared__ float tile[32][33];
    int b = blockIdx.z;
    int n0 = blockIdx.x * 32, c0 = blockIdx.y * 32;
    int tx = threadIdx.x, ty = threadIdx.y;
    const float* xp = x + (size_t)b * NC * NT;
    #pragma unroll
    for (int i = 0; i < 4; i++) {
        int c = c0 + ty + i * 8;
        tile[ty + i * 8][tx] = xp[(size_t)c * NT + n0 + tx];
    }
    __syncthreads();
    float* fp = buf_feats + (size_t)b * NT * NC;
    #pragma unroll
    for (int i = 0; i < 4; i++) {
        int n = n0 + ty + i * 8;
        fp[(size_t)n * NC + c0 + tx] = tile[tx][ty + i * 8];
    }
}

// ---------------- big fp32 GEMM (precompute) ----------------
// kvmode=1: scatter output to head-major [b][h][n][d]
__global__ void gemm_f32(const float* __restrict__ A, int lda,
                         const float* __restrict__ B, int ldb,
                         const float* __restrict__ bias,
                         float* __restrict__ C, int ldc, int K, int kvmode) {
    __shared__ float As[16][128 + 4];
    __shared__ float Bs[16][64];
    const int tid = threadIdx.x;
    const int tx = tid & 15;
    const int ty = tid >> 4;
    const int row0 = blockIdx.y * 128;
    const int col0 = blockIdx.x * 64;
    float acc[8][4];
    #pragma unroll
    for (int i = 0; i < 8; i++)
        #pragma unroll
        for (int j = 0; j < 4; j++) acc[i][j] = 0.f;

    for (int k0 = 0; k0 < K; k0 += 16) {
        #pragma unroll
        for (int i = 0; i < 8; i++) {
            int e = tid + i * 256;
            int r = e >> 4, kk = e & 15;
            As[kk][r] = A[(size_t)(row0 + r) * lda + k0 + kk];
        }
        #pragma unroll
        for (int i = 0; i < 4; i++) {
            int e = tid + i * 256;
            int kk = e >> 6, n = e & 63;
            Bs[kk][n] = B[(size_t)(k0 + kk) * ldb + col0 + n];
        }
        __syncthreads();
        #pragma unroll
        for (int kk = 0; kk < 16; kk++) {
            float a[8], bb[4];
            #pragma unroll
            for (int i = 0; i < 8; i++) a[i] = As[kk][ty * 8 + i];
            #pragma unroll
            for (int j = 0; j < 4; j++) bb[j] = Bs[kk][tx * 4 + j];
            #pragma unroll
            for (int i = 0; i < 8; i++)
                #pragma unroll
                for (int j = 0; j < 4; j++)
                    acc[i][j] += a[i] * bb[j];
        }
        __syncthreads();
    }
    #pragma unroll
    for (int i = 0; i < 8; i++) {
        int r = row0 + ty * 8 + i;
        #pragma unroll
        for (int j = 0; j < 4; j++) {
            int c = col0 + tx * 4 + j;
            float val = acc[i][j] + (bias ? bias[c] : 0.f);
            if (!kvmode) {
                C[(size_t)r * ldc + c] = val;
            } else {
                int b = r >> 10, n = r & 1023, h = c >> 6, d = c & 63;
                C[((((size_t)b * NH + h) << 10) + n) * HD + d] = val;
            }
        }
    }
}

// ---------------- row LayerNorm ----------------
__global__ void ln_rows(float* __restrict__ X, int L,
                        const float* __restrict__ g, const float* __restrict__ b) {
    int row = blockIdx.x;
    float* xp = X + (size_t)row * L;
    float s = 0.f;
    for (int i = threadIdx.x; i < L; i += blockDim.x) s += xp[i];
    s = blockReduceSum(s);
    float m = s / L;
    float v = 0.f;
    for (int i = threadIdx.x; i < L; i += blockDim.x) { float d = xp[i] - m; v += d * d; }
    v = blockReduceSum(v);
    float inv = rsqrtf(v / L + 1e-5f);
    for (int i = threadIdx.x; i < L; i += blockDim.x)
        xp[i] = (xp[i] - m) * inv * g[i] + b[i];
}

__global__ void make_bqq(const float* __restrict__ b_q, const float* __restrict__ W_in,
                         const float* __restrict__ b_in) {
    int j = blockIdx.x * blockDim.x + threadIdx.x;
    if (j >= NE) return;
    float s = b_in[j];
    for (int k = 0; k < NE; k++) s += b_q[k] * W_in[(size_t)k * (3 * NE) + j];
    buf_bqq[j] = s;
}

__global__ void init_state(const float* __restrict__ start) {
    int i = blockIdx.x * blockDim.x + threadIdx.x;
    if (i < NB * ND) buf_act[i] = start[i & (ND - 1)];
    if (i < NB * NA_) { buf_aA[i] = 0.f; buf_bA[i] = 0.f; buf_aO[i] = 0.f; buf_bO[i] = 0.f; }
}

// ---------------- sync updates ----------------
__global__ void syncA_update(const int* __restrict__ idx, const float* __restrict__ decay) {
    int b = blockIdx.x, i = threadIdx.x;
    float r = expf(-fminf(fmaxf(decay[i], 0.f), 15.f));
    float sel = buf_act[b * ND + idx[i]];
    float a = r * buf_aA[b * NA_ + i] + sel * sel;
    float bb = r * buf_bA[b * NA_ + i] + 1.f;
    buf_aA[b * NA_ + i] = a;
    buf_bA[b * NA_ + i] = bb;
    buf_syncA[b * NA_ + i] = a * rsqrtf(bb);
}

__global__ void syncO_update(const int* __restrict__ idx, const float* __restrict__ decay,
                             float* __restrict__ dout, int t) {
    int b = blockIdx.x, i = threadIdx.x;
    float r = expf(-fminf(fmaxf(decay[i], 0.f), 15.f));
    float sel = buf_act[b * ND + idx[i]];
    float a = r * buf_aO[b * NO_ + i] + sel * sel;
    float bb = r * buf_bO[b * NO_ + i] + 1.f;
    buf_aO[b * NO_ + i] = a;
    buf_bO[b * NO_ + i] = bb;
    float sy = a * rsqrtf(bb);
    buf_syncO[b * NO_ + i] = sy;
    if (t == NSTEP - 1) dout[SYNC_BASE + b * NO_ + i] = sy;
}

// ---------------- pipelined split-K skinny GEMM ----------------
// M=32 rows. grid = (ceil(Nout/64), nsplit). 256 threads.
// part[(split*32 + r)*Nout + col] = Sum_{k in chunk} A[r][k] * B[k][col]
// A = [A0 (K0 cols) | A1 (K1 cols)], row-major.
#define SKS 4
__global__ void skinny_gemm(const float* __restrict__ A0, int K0,
                            const float* __restrict__ A1, int K1,
                            const float* __restrict__ B, int ldb,
                            float* __restrict__ part, int Nout, int Kper) {
    __shared__ float As[SKS][32][16];
    __shared__ float Bs[SKS][16][64];
    const int tid = threadIdx.x;
    const int col0 = blockIdx.x * 64;
    const int kstart = blockIdx.y * Kper;
    const int ntiles = Kper >> 4;

    // load thread mappings
    const int b_kk = tid >> 4;            // 0..15
    const int b_c  = (tid & 15) * 4;      // 0..60
    const int a_r  = tid >> 2;            // 0..63 (use <32 only => tid<128)
    const int a_kc = (tid & 3) * 4;       // 0,4,8,12
    int bcol = col0 + b_c;
    if (bcol > Nout - 4) bcol = Nout - 4; // clamp (values unused at store)

    // compute thread mapping
    const int c4 = (tid & 15) * 4;
    const int r0 = (tid >> 4) * 2;

    float acc[2][4];
    #pragma unroll
    for (int i = 0; i < 2; i++)
        #pragma unroll
        for (int j = 0; j < 4; j++) acc[i][j] = 0.f;

    // prologue: issue SKS-1 tiles
    #pragma unroll
    for (int pt = 0; pt < SKS - 1; pt++) {
        if (pt < ntiles) {
            int kb = kstart + pt * 16;
            cp16(&Bs[pt][b_kk][b_c], B + (size_t)(kb + b_kk) * ldb + bcol);
            if (tid < 128) {
                int k = kb + a_kc;
                const float* src = (k < K0) ? (A0 + (size_t)a_r * K0 + k)
                                            : (A1 + (size_t)a_r * K1 + (k - K0));
                cp16(&As[pt][a_r][a_kc], src);
            }
        }
        CP_COMMIT();
    }

    for (int ct = 0; ct < ntiles; ct++) {
        CP_WAIT2();
        __syncthreads();
        const int st = ct & (SKS - 1);
        #pragma unroll
        for (int kk = 0; kk < 16; kk++) {
            float4 bv = *(const float4*)&Bs[st][kk][c4];
            float a0 = As[st][r0][kk];
            float a1 = As[st][r0 + 1][kk];
            acc[0][0] += a0 * bv.x; acc[0][1] += a0 * bv.y;
            acc[0][2] += a0 * bv.z; acc[0][3] += a0 * bv.w;
            acc[1][0] += a1 * bv.x; acc[1][1] += a1 * bv.y;
            acc[1][2] += a1 * bv.z; acc[1][3] += a1 * bv.w;
        }
        __syncthreads();
        int nt = ct + SKS - 1;
        if (nt < ntiles) {
            int kb = kstart + nt * 16;
            int st2 = nt & (SKS - 1);
            cp16(&Bs[st2][b_kk][b_c], B + (size_t)(kb + b_kk) * ldb + bcol);
            if (tid < 128) {
                int k = kb + a_kc;
                const float* src = (k < K0) ? (A0 + (size_t)a_r * K0 + k)
                                            : (A1 + (size_t)a_r * K1 + (k - K0));
                cp16(&As[st2][a_r][a_kc], src);
            }
        }
        CP_COMMIT();
    }

    float* po = part + ((size_t)blockIdx.y * 32 + r0) * Nout;
    #pragma unroll
    for (int j = 0; j < 4; j++) {
        int c = col0 + c4 + j;
        if (c < Nout) {
            po[c] = acc[0][j];
            po[Nout + c] = acc[1][j];
        }
    }
}

// ---------------- split-K reduce (+bias, optional relu) ----------------
__global__ void reduce_rows(const float* __restrict__ part, const float* __restrict__ bias,
                            float* __restrict__ out, int Nout, int nsplit, int relu) {
    int i = blockIdx.x * 256 + threadIdx.x;
    if (i >= 32 * Nout) return;
    int r = i / Nout, c = i - r * Nout;
    float s = bias[c];
    for (int k = 0; k < nsplit; k++) s += part[((size_t)k * 32 + r) * Nout + c];
    out[i] = relu ? fmaxf(s, 0.f) : s;
}

// ---------------- attention: partial over 128-token chunks ----------------
__global__ void attn_partial(const float* __restrict__ dummy) {
    const int bh = blockIdx.x >> 3;
    const int chunk = blockIdx.x & 7;
    const int b = bh >> 3, h = bh & 7;
    const int tid = threadIdx.x;
    __shared__ float qs[64];
    __shared__ float ev[128];
    __shared__ float red[4][64];

    if (tid < 64) {
        float q = buf_bqq[h * HD + tid];
        #pragma unroll
        for (int s = 0; s < 8; s++) q += buf_qpart[((size_t)s * 32 + b) * NE + h * HD + tid];
        qs[tid] = q;
    }
    __syncthreads();

    // scores
    const int lane = tid & 31, w = tid >> 5;
    const float* Kb = buf_K + (((size_t)bh << 10) + chunk * 128) * HD;
    for (int i = w; i < 128; i += 8) {
        float2 k2 = *(const float2*)(Kb + (size_t)i * HD + lane * 2);
        float p = qs[lane * 2] * k2.x + qs[lane * 2 + 1] * k2.y;
        #pragma unroll
        for (int o = 16; o; o >>= 1) p += __shfl_xor_sync(0xffffffffu, p, o);
        if (lane == 0) ev[i] = p * 0.125f;
    }
    __syncthreads();

    float m = (tid < 128) ? ev[tid] : -1e30f;
    m = blockReduceMax(m);
    float e = (tid < 128) ? expf(ev[tid] - m) : 0.f;
    float s = blockReduceSum(e);
    if (tid < 128) ev[tid] = e;
    __syncthreads();

    // weighted V (unnormalized, local max frame)
    const int d = tid & 63, g = tid >> 6;
    const float* Vb = buf_V + (((size_t)bh << 10) + chunk * 128) * HD + d;
    float acc = 0.f;
    #pragma unroll 8
    for (int n = g * 32; n < g * 32 + 32; n++)
        acc += ev[n] * Vb[(size_t)n * HD];
    red[g][d] = acc;
    __syncthreads();
    if (tid < 64) {
        float v = red[0][tid] + red[1][tid] + red[2][tid] + red[3][tid];
        buf_pv[(size_t)blockIdx.x * HD + tid] = v;
        if (tid == 0) { buf_pm[blockIdx.x] = m; buf_ps[blockIdx.x] = s; }
    }
}

__global__ void attn_combine() {
    const int bh = blockIdx.x;
    const int b = bh >> 3, h = bh & 7;
    const int tid = threadIdx.x; // 64
    float M = -1e30f;
    #pragma unroll
    for (int c = 0; c < 8; c++) M = fmaxf(M, buf_pm[bh * 8 + c]);
    float T = 0.f, v = 0.f;
    #pragma unroll
    for (int c = 0; c < 8; c++) {
        float w = expf(buf_pm[bh * 8 + c] - M);
        T += buf_ps[bh * 8 + c] * w;
        v += buf_pv[(size_t)(bh * 8 + c) * HD + tid] * w;
    }
    buf_attn[b * NE + h * HD + tid] = v / T;
}

// ---------------- fused split-K reduce + GLU + double LN ----------------
__global__ void glu_ln_ln(const float* __restrict__ b_syn,
                          const float* __restrict__ g_syn, const float* __restrict__ be_syn,
                          const float* __restrict__ g_pm, const float* __restrict__ be_pm) {
    int b = blockIdx.x, tid = threadIdx.x;
    float v[8];
    #pragma unroll
    for (int j = 0; j < 8; j++) {
        int d = tid + j * 256;
        float a = b_syn[d], gg = b_syn[ND + d];
        #pragma unroll
        for (int s = 0; s < 8; s++) {
            const float* hp = buf_hpart + ((size_t)s * 32 + b) * (2 * ND);
            a += hp[d];
            gg += hp[ND + d];
        }
        v[j] = a * (1.f / (1.f + expf(-gg)));
    }
    float s = 0.f;
    #pragma unroll
    for (int j = 0; j < 8; j++) s += v[j];
    s = blockReduceSum(s);
    float m = s / ND;
    float var = 0.f;
    #pragma unroll
    for (int j = 0; j < 8; j++) { float d = v[j] - m; var += d * d; }
    var = blockReduceSum(var);
    float inv = rsqrtf(var / ND + 1e-5f);
    #pragma unroll
    for (int j = 0; j < 8; j++) {
        int d = tid + j * 256;
        v[j] = (v[j] - m) * inv * g_syn[d] + be_syn[d];
    }
    s = 0.f;
    #pragma unroll
    for (int j = 0; j < 8; j++) s += v[j];
    s = blockReduceSum(s);
    float m2 = s / ND;
    var = 0.f;
    #pragma unroll
    for (int j = 0; j < 8; j++) { float d = v[j] - m2; var += d * d; }
    var = blockReduceSum(var);
    float inv2 = rsqrtf(var / ND + 1e-5f);
    #pragma unroll
    for (int j = 0; j < 8; j++) {
        int d = tid + j * 256;
        buf_hpm[(size_t)b * ND + d] = (v[j] - m2) * inv2 * g_pm[d] + be_pm[d];
    }
}

// ---------------- fused pred reduce + entropy + writes ----------------
__global__ void entropy_write(const float* __restrict__ b_out, float* __restrict__ dout, int t) {
    int b = blockIdx.x, tid = threadIdx.x;
    __shared__ float sp[NOUT];
    for (int i = tid; i < NOUT; i += 256)
        sp[i] = b_out[i] + buf_predpart[(size_t)b * NOUT + i]
                         + buf_predpart[((size_t)32 + b) * NOUT + i];
    __syncthreads();
    float m = -1e30f;
    for (int i = tid; i < NOUT; i += 256) m = fmaxf(m, sp[i]);
    m = blockReduceMax(m);
    float s = 0.f;
    for (int i = tid; i < NOUT; i += 256) s += expf(sp[i] - m);
    s = blockReduceSum(s);
    float lse = m + logf(s);
    float ent = 0.f;
    for (int i = tid; i < NOUT; i += 256) {
        float pv = sp[i];
        float lp = pv - lse;
        ent += expf(lp) * lp;
        dout[(size_t)b * NOUT * NSTEP + (size_t)i * NSTEP + t] = pv;
    }
    ent = blockReduceSum(ent);
    if (tid == 0) {
        float ne = -ent / logf((float)NOUT);
        dout[CERT_BASE + b * (2 * NSTEP) + t] = ne;
        dout[CERT_BASE + b * (2 * NSTEP) + NSTEP + t] = 1.f - ne;
    }
}

// ---------------- launch ----------------
extern "C" void kernel_launch(void* const* d_in, const int* in_sizes, int n_in,
                              void* d_out, int out_size) {
    const float* x     = (const float*)d_in[0];
    const float* W_kv  = (const float*)d_in[1];
    const float* b_kv  = (const float*)d_in[2];
    const float* g_kv  = (const float*)d_in[3];
    const float* be_kv = (const float*)d_in[4];
    const float* W_q   = (const float*)d_in[5];
    const float* b_q   = (const float*)d_in[6];
    const float* W_in  = (const float*)d_in[7];
    const float* b_in  = (const float*)d_in[8];
    const float* W_ao  = (const float*)d_in[9];
    const float* b_ao  = (const float*)d_in[10];
    const float* W_syn = (const float*)d_in[11];
    const float* b_syn = (const float*)d_in[12];
    const float* g_syn = (const float*)d_in[13];
    const float* be_syn= (const float*)d_in[14];
    const float* g_pm  = (const float*)d_in[15];
    const float* be_pm = (const float*)d_in[16];
    const float* W1    = (const float*)d_in[17];
    const float* b1    = (const float*)d_in[18];
    const float* W2    = (const float*)d_in[19];
    const float* b2    = (const float*)d_in[20];
    const float* start = (const float*)d_in[21];
    const float* dec_a = (const float*)d_in[22];
    const float* dec_o = (const float*)d_in[23];
    const float* W_out = (const float*)d_in[24];
    const float* b_out = (const float*)d_in[25];
    const int*   idx_a = (const int*)d_in[26];
    const int*   idx_o = (const int*)d_in[27];
    float* out = (float*)d_out;

    float *p_feats, *p_kv, *p_K, *p_V, *p_Wqq;
    float *p_syncA, *p_attn, *p_attno, *p_act, *p_hpm, *p_t1, *p_syncO;
    float *p_qpart, *p_attnopart, *p_hpart, *p_w1part, *p_w2part, *p_predpart;
    cudaGetSymbolAddress((void**)&p_feats, buf_feats);
    cudaGetSymbolAddress((void**)&p_kv,    buf_kv);
    cudaGetSymbolAddress((void**)&p_K,     buf_K);
    cudaGetSymbolAddress((void**)&p_V,     buf_V);
    cudaGetSymbolAddress((void**)&p_Wqq,   buf_Wqq);
    cudaGetSymbolAddress((void**)&p_syncA, buf_syncA);
    cudaGetSymbolAddress((void**)&p_attn,  buf_attn);
    cudaGetSymbolAddress((void**)&p_attno, buf_attno);
    cudaGetSymbolAddress((void**)&p_act,   buf_act);
    cudaGetSymbolAddress((void**)&p_hpm,   buf_hpm);
    cudaGetSymbolAddress((void**)&p_t1,    buf_t1);
    cudaGetSymbolAddress((void**)&p_syncO, buf_syncO);
    cudaGetSymbolAddress((void**)&p_qpart,    buf_qpart);
    cudaGetSymbolAddress((void**)&p_attnopart, buf_attnopart);
    cudaGetSymbolAddress((void**)&p_hpart,    buf_hpart);
    cudaGetSymbolAddress((void**)&p_w1part,   buf_w1part);
    cudaGetSymbolAddress((void**)&p_w2part,   buf_w2part);
    cudaGetSymbolAddress((void**)&p_predpart, buf_predpart);

    // ---- precompute ----
    transpose_x<<<dim3(NT / 32, NC / 32, NB), dim3(32, 8)>>>(x);
    gemm_f32<<<dim3(NE / 64, (NB * NT) / 128), 256>>>(p_feats, NC, W_kv, NE, b_kv, p_kv, NE, NC, 0);
    ln_rows<<<NB * NT, 256>>>(p_kv, NE, g_kv, be_kv);
    gemm_f32<<<dim3(NE / 64, (NB * NT) / 128), 256>>>(p_kv, NE, W_in + NE,     3 * NE, b_in + NE,     p_K, NE, NE, 1);
    gemm_f32<<<dim3(NE / 64, (NB * NT) / 128), 256>>>(p_kv, NE, W_in + 2 * NE, 3 * NE, b_in + 2 * NE, p_V, NE, NE, 1);
    gemm_f32<<<dim3(NE / 64, NE / 128), 256>>>(W_q, NE, W_in, 3 * NE, (const float*)0, p_Wqq, NE, NE, 0);
    make_bqq<<<2, 256>>>(b_q, W_in, b_in);
    init_state<<<(NB * ND + 255) / 256, 256>>>(start);

    // ---- recurrent loop ----
    for (int t = 0; t < NSTEP; t++) {
        syncA_update<<<NB, NA_>>>(idx_a, dec_a);
        // qh partials: syncA @ Wqq, split 8
        skinny_gemm<<<dim3(NE / 64, 8), 256>>>(p_syncA, NA_, (const float*)0, 0,
                                               p_Wqq, NE, p_qpart, NE, NA_ / 8);
        attn_partial<<<NB * NH * 8, 256>>>((const float*)0);
        attn_combine<<<NB * NH, 64>>>();
        // attno: attn @ W_ao, split 4
        skinny_gemm<<<dim3(NE / 64, 4), 256>>>(p_attn, NE, (const float*)0, 0,
                                               W_ao, NE, p_attnopart, NE, NE / 4);
        reduce_rows<<<(32 * NE + 255) / 256, 256>>>(p_attnopart, b_ao, p_attno, NE, 4, 0);
        // h: [attno|act] @ W_syn, split 8
        skinny_gemm<<<dim3((2 * ND) / 64, 8), 256>>>(p_attno, NE, p_act, ND,
                                                     W_syn, 2 * ND, p_hpart, 2 * ND, (NE + ND) / 8);
        glu_ln_ln<<<NB, 256>>>(b_syn, g_syn, be_syn, g_pm, be_pm);
        // t1 = relu(hpm@W1+b1), split 4
        skinny_gemm<<<dim3(ND / 64, 4), 256>>>(p_hpm, ND, (const float*)0, 0,
                                               W1, ND, p_w1part, ND, ND / 4);
        reduce_rows<<<(32 * ND + 255) / 256, 256>>>(p_w1part, b1, p_t1, ND, 4, 1);
        // act = relu(t1@W2+b2), split 4
        skinny_gemm<<<dim3(ND / 64, 4), 256>>>(p_t1, ND, (const float*)0, 0,
                                               W2, ND, p_w2part, ND, ND / 4);
        reduce_rows<<<(32 * ND + 255) / 256, 256>>>(p_w2part, b2, p_act, ND, 4, 1);
        syncO_update<<<NB, NO_>>>(idx_o, dec_o, out, t);
        // pred partials: syncO @ W_out, split 2
        skinny_gemm<<<dim3((NOUT + 63) / 64, 2), 256>>>(p_syncO, NO_, (const float*)0, 0,
                                                        W_out, NOUT, p_predpart, NOUT, NO_ / 2);
        entropy_write<<<NB, 256>>>(b_out, out, t);
    }
}

// round 4
// speedup vs baseline: 7.9633x; 1.1256x over previous
#include <cuda_runtime.h>
#include <math.h>
#include <stdint.h>

// ---------------- problem dims ----------------
#define NB 32
#define NC 512
#define NT 1024
#define NE 512
#define ND 2048
#define NH 8
#define HD 64
#define NSTEP 50
#define NOUT 1000
#define NA_ 512
#define NO_ 512

#define PRED_ELEMS (NB*NOUT*NSTEP)
#define CERT_BASE  PRED_ELEMS
#define SYNC_BASE  (CERT_BASE + NB*2*NSTEP)

// ---------------- device scratch ----------------
__device__ float buf_feats[NB*NT*NC];
__device__ float buf_kv   [NB*NT*NE];
__device__ float buf_K    [NB*NT*NE];   // TRANSPOSED head-major: [b][h][d][n]
__device__ float buf_V    [NB*NT*NE];   // head-major: [b][h][n][d]
__device__ float buf_act  [NB*ND];
__device__ float buf_aA   [NB*NA_];
__device__ float buf_bA   [NB*NA_];
__device__ float buf_syncA[NB*NA_];
__device__ float buf_aO   [NB*NO_];
__device__ float buf_bO   [NB*NO_];
__device__ float buf_syncO[NB*NO_];
__device__ float buf_attn [NB*NE];
__device__ float buf_attno[NB*NE];
__device__ float buf_hpm  [NB*ND];
__device__ float buf_t1   [NB*ND];
__device__ float buf_Wqq  [NE*NE];
__device__ float buf_bqq  [NE];
// split-K partials
__device__ float buf_qpart    [8*32*NE];
__device__ float buf_attnopart[4*32*NE];
__device__ float buf_hpart    [8*32*2*ND];
__device__ float buf_w1part   [4*32*ND];
__device__ float buf_w2part   [4*32*ND];
__device__ float buf_predpart [2*32*NOUT];
// attention partials
__device__ float buf_pv[NB*NH*8*HD];
__device__ float buf_pm[NB*NH*8];
__device__ float buf_ps[NB*NH*8];

// ---------------- cp.async helpers ----------------
__device__ __forceinline__ void cp16(void* smem, const void* gmem) {
    uint32_t s = (uint32_t)__cvta_generic_to_shared(smem);
    asm volatile("cp.async.cg.shared.global [%0], [%1], 16;\n" :: "r"(s), "l"(gmem));
}
#define CP_COMMIT() asm volatile("cp.async.commit_group;\n" ::: "memory")
#define CP_WAIT2()  asm volatile("cp.async.wait_group 2;\n" ::: "memory")
#define CP_WAIT1()  asm volatile("cp.async.wait_group 1;\n" ::: "memory")

// ---------------- tf32 mma helpers ----------------
__device__ __forceinline__ uint32_t f2tf(float x) {
    uint32_t r;
    asm("cvt.rna.tf32.f32 %0, %1;" : "=r"(r) : "f"(x));
    return r;
}
__device__ __forceinline__ void mma_tf32(float* c, const uint32_t* a, const uint32_t* b) {
    asm volatile(
        "mma.sync.aligned.m16n8k8.row.col.f32.tf32.tf32.f32 "
        "{%0,%1,%2,%3},{%4,%5,%6,%7},{%8,%9},{%0,%1,%2,%3};"
        : "+f"(c[0]), "+f"(c[1]), "+f"(c[2]), "+f"(c[3])
        : "r"(a[0]), "r"(a[1]), "r"(a[2]), "r"(a[3]), "r"(b[0]), "r"(b[1]));
}

// ---------------- block reductions ----------------
__device__ __forceinline__ float blockReduceSum(float v) {
    __shared__ float shs[32];
    int lane = threadIdx.x & 31, w = threadIdx.x >> 5;
    #pragma unroll
    for (int o = 16; o; o >>= 1) v += __shfl_xor_sync(0xffffffffu, v, o);
    if (lane == 0) shs[w] = v;
    __syncthreads();
    float r = 0.f;
    int nw = (blockDim.x + 31) >> 5;
    if (threadIdx.x < nw) r = shs[threadIdx.x];
    if (w == 0) {
        #pragma unroll
        for (int o = 16; o; o >>= 1) r += __shfl_xor_sync(0xffffffffu, r, o);
        if (lane == 0) shs[0] = r;
    }
    __syncthreads();
    float out = shs[0];
    __syncthreads();
    return out;
}
__device__ __forceinline__ float blockReduceMax(float v) {
    __shared__ float shm[32];
    int lane = threadIdx.x & 31, w = threadIdx.x >> 5;
    #pragma unroll
    for (int o = 16; o; o >>= 1) v = fmaxf(v, __shfl_xor_sync(0xffffffffu, v, o));
    if (lane == 0) shm[w] = v;
    __syncthreads();
    float r = -1e30f;
    int nw = (blockDim.x + 31) >> 5;
    if (threadIdx.x < nw) r = shm[threadIdx.x];
    if (w == 0) {
        #pragma unroll
        for (int o = 16; o; o >>= 1) r = fmaxf(r, __shfl_xor_sync(0xffffffffu, r, o));
        if (lane == 0) shm[0] = r;
    }
    __syncthreads();
    float out = shm[0];
    __syncthreads();
    return out;
}

// ---------------- transpose ----------------
__global__ void transpose_x(const float* __restrict__ x) {
    __shared__ float tile[32][33];
    int b = blockIdx.z;
    int n0 = blockIdx.x * 32, c0 = blockIdx.y * 32;
    int tx = threadIdx.x, ty = threadIdx.y;
    const float* xp = x + (size_t)b * NC * NT;
    #pragma unroll
    for (int i = 0; i < 4; i++) {
        int c = c0 + ty + i * 8;
        tile[ty + i * 8][tx] = xp[(size_t)c * NT + n0 + tx];
    }
    __syncthreads();
    float* fp = buf_feats + (size_t)b * NT * NC;
    #pragma unroll
    for (int i = 0; i < 4; i++) {
        int n = n0 + ty + i * 8;
        fp[(size_t)n * NC + c0 + tx] = tile[tx][ty + i * 8];
    }
}

// ---------------- tf32 tensor-core GEMM (precompute) ----------------
// C[M,N] = A@B (+bias). BM=128, BN=64, BK=16, 256 thr, 8 warps (4m x 2n).
// kvmode: 0 = plain row-major store; 1 = K^T scatter [b][h][d][n]; 2 = V scatter [b][h][n][d]
__global__ void gemm_tf32(const float* __restrict__ A, int lda,
                          const float* __restrict__ B, int ldb,
                          const float* __restrict__ bias,
                          float* __restrict__ C, int ldc, int K, int kvmode) {
    __shared__ float As[2][128][20];
    __shared__ float Bs[2][16][68];
    const int tid = threadIdx.x;
    const int wid = tid >> 5, lane = tid & 31;
    const int g = lane >> 2, tg = lane & 3;
    const int warp_m = wid >> 1, warp_n = wid & 1;
    const int row0 = blockIdx.y * 128;
    const int col0 = blockIdx.x * 64;

    // load mappings
    const int la_r = tid >> 1;              // 0..127
    const int la_c = (tid & 1) * 8;         // 0 or 8
    const int lb_r = tid >> 4;              // 0..15
    const int lb_c = (tid & 15) * 4;        // 0..60

    float acc[2][4][4];
    #pragma unroll
    for (int mi = 0; mi < 2; mi++)
        #pragma unroll
        for (int ni = 0; ni < 4; ni++)
            #pragma unroll
            for (int j = 0; j < 4; j++) acc[mi][ni][j] = 0.f;

    const int ntiles = K >> 4;

    // prologue: tile 0 into stage 0
    {
        const float* ap = A + (size_t)(row0 + la_r) * lda + la_c;
        cp16(&As[0][la_r][la_c], ap);
        cp16(&As[0][la_r][la_c + 4], ap + 4);
        cp16(&Bs[0][lb_r][lb_c], B + (size_t)lb_r * ldb + col0 + lb_c);
    }
    CP_COMMIT();

    for (int ct = 0; ct < ntiles; ct++) {
        if (ct + 1 < ntiles) {
            int k0 = (ct + 1) << 4;
            int st = (ct + 1) & 1;
            const float* ap = A + (size_t)(row0 + la_r) * lda + k0 + la_c;
            cp16(&As[st][la_r][la_c], ap);
            cp16(&As[st][la_r][la_c + 4], ap + 4);
            cp16(&Bs[st][lb_r][lb_c], B + (size_t)(k0 + lb_r) * ldb + col0 + lb_c);
        }
        CP_COMMIT();
        CP_WAIT1();
        __syncthreads();
        const int st = ct & 1;
        #pragma unroll
        for (int ks = 0; ks < 2; ks++) {
            const int k8 = ks * 8;
            uint32_t a[2][4], bf[4][2];
            #pragma unroll
            for (int mi = 0; mi < 2; mi++) {
                int r = warp_m * 32 + mi * 16 + g;
                a[mi][0] = f2tf(As[st][r][k8 + tg]);
                a[mi][1] = f2tf(As[st][r + 8][k8 + tg]);
                a[mi][2] = f2tf(As[st][r][k8 + tg + 4]);
                a[mi][3] = f2tf(As[st][r + 8][k8 + tg + 4]);
            }
            #pragma unroll
            for (int ni = 0; ni < 4; ni++) {
                int c = warp_n * 32 + ni * 8 + g;
                bf[ni][0] = f2tf(Bs[st][k8 + tg][c]);
                bf[ni][1] = f2tf(Bs[st][k8 + tg + 4][c]);
            }
            #pragma unroll
            for (int mi = 0; mi < 2; mi++)
                #pragma unroll
                for (int ni = 0; ni < 4; ni++)
                    mma_tf32(acc[mi][ni], a[mi], bf[ni]);
        }
        __syncthreads();
    }

    // store
    #pragma unroll
    for (int mi = 0; mi < 2; mi++) {
        #pragma unroll
        for (int ni = 0; ni < 4; ni++) {
            int r = row0 + warp_m * 32 + mi * 16 + g;
            int c = col0 + warp_n * 32 + ni * 8 + 2 * tg;
            float b0 = bias ? bias[c] : 0.f;
            float b1 = bias ? bias[c + 1] : 0.f;
            float v00 = acc[mi][ni][0] + b0, v01 = acc[mi][ni][1] + b1;
            float v10 = acc[mi][ni][2] + b0, v11 = acc[mi][ni][3] + b1;
            #pragma unroll
            for (int rr = 0; rr < 2; rr++) {
                int row = r + rr * 8;
                float va = rr ? v10 : v00;
                float vb = rr ? v11 : v01;
                if (kvmode == 0) {
                    C[(size_t)row * ldc + c] = va;
                    C[(size_t)row * ldc + c + 1] = vb;
                } else if (kvmode == 1) {
                    int b = row >> 10, n = row & 1023;
                    int h0 = c >> 6, d0 = c & 63;
                    int h1 = (c + 1) >> 6, d1 = (c + 1) & 63;
                    C[(((size_t)(b * NH + h0)) * HD + d0) * NT + n] = va;
                    C[(((size_t)(b * NH + h1)) * HD + d1) * NT + n] = vb;
                } else {
                    int b = row >> 10, n = row & 1023;
                    int h0 = c >> 6, d0 = c & 63;
                    int h1 = (c + 1) >> 6, d1 = (c + 1) & 63;
                    C[((((size_t)b * NH + h0) << 10) + n) * HD + d0] = va;
                    C[((((size_t)b * NH + h1) << 10) + n) * HD + d1] = vb;
                }
            }
        }
    }
}

// ---------------- row LayerNorm ----------------
__global__ void ln_rows(float* __restrict__ X, int L,
                        const float* __restrict__ g, const float* __restrict__ b) {
    int row = blockIdx.x;
    float* xp = X + (size_t)row * L;
    float s = 0.f;
    for (int i = threadIdx.x; i < L; i += blockDim.x) s += xp[i];
    s = blockReduceSum(s);
    float m = s / L;
    float v = 0.f;
    for (int i = threadIdx.x; i < L; i += blockDim.x) { float d = xp[i] - m; v += d * d; }
    v = blockReduceSum(v);
    float inv = rsqrtf(v / L + 1e-5f);
    for (int i = threadIdx.x; i < L; i += blockDim.x)
        xp[i] = (xp[i] - m) * inv * g[i] + b[i];
}

__global__ void make_bqq(const float* __restrict__ b_q, const float* __restrict__ W_in,
                         const float* __restrict__ b_in) {
    int j = blockIdx.x * blockDim.x + threadIdx.x;
    if (j >= NE) return;
    float s = b_in[j];
    for (int k = 0; k < NE; k++) s += b_q[k] * W_in[(size_t)k * (3 * NE) + j];
    buf_bqq[j] = s;
}

__global__ void init_state(const float* __restrict__ start) {
    int i = blockIdx.x * blockDim.x + threadIdx.x;
    if (i < NB * ND) buf_act[i] = start[i & (ND - 1)];
    if (i < NB * NA_) { buf_aA[i] = 0.f; buf_bA[i] = 0.f; buf_aO[i] = 0.f; buf_bO[i] = 0.f; }
}

// ---------------- sync updates ----------------
__global__ void syncA_update(const int* __restrict__ idx, const float* __restrict__ decay) {
    int b = blockIdx.x, i = threadIdx.x;
    float r = expf(-fminf(fmaxf(decay[i], 0.f), 15.f));
    float sel = buf_act[b * ND + idx[i]];
    float a = r * buf_aA[b * NA_ + i] + sel * sel;
    float bb = r * buf_bA[b * NA_ + i] + 1.f;
    buf_aA[b * NA_ + i] = a;
    buf_bA[b * NA_ + i] = bb;
    buf_syncA[b * NA_ + i] = a * rsqrtf(bb);
}

__global__ void syncO_update(const int* __restrict__ idx, const float* __restrict__ decay,
                             float* __restrict__ dout, int t) {
    int b = blockIdx.x, i = threadIdx.x;
    float r = expf(-fminf(fmaxf(decay[i], 0.f), 15.f));
    float sel = buf_act[b * ND + idx[i]];
    float a = r * buf_aO[b * NO_ + i] + sel * sel;
    float bb = r * buf_bO[b * NO_ + i] + 1.f;
    buf_aO[b * NO_ + i] = a;
    buf_bO[b * NO_ + i] = bb;
    float sy = a * rsqrtf(bb);
    buf_syncO[b * NO_ + i] = sy;
    if (t == NSTEP - 1) dout[SYNC_BASE + b * NO_ + i] = sy;
}

// ---------------- pipelined split-K skinny GEMM ----------------
#define SKS 4
__global__ void skinny_gemm(const float* __restrict__ A0, int K0,
                            const float* __restrict__ A1, int K1,
                            const float* __restrict__ B, int ldb,
                            float* __restrict__ part, int Nout, int Kper) {
    __shared__ float As[SKS][32][16];
    __shared__ float Bs[SKS][16][64];
    const int tid = threadIdx.x;
    const int col0 = blockIdx.x * 64;
    const int kstart = blockIdx.y * Kper;
    const int ntiles = Kper >> 4;

    const int b_kk = tid >> 4;
    const int b_c  = (tid & 15) * 4;
    const int a_r  = tid >> 2;
    const int a_kc = (tid & 3) * 4;
    int bcol = col0 + b_c;
    if (bcol > Nout - 4) bcol = Nout - 4;

    const int c4 = (tid & 15) * 4;
    const int r0 = (tid >> 4) * 2;

    float acc[2][4];
    #pragma unroll
    for (int i = 0; i < 2; i++)
        #pragma unroll
        for (int j = 0; j < 4; j++) acc[i][j] = 0.f;

    #pragma unroll
    for (int pt = 0; pt < SKS - 1; pt++) {
        if (pt < ntiles) {
            int kb = kstart + pt * 16;
            cp16(&Bs[pt][b_kk][b_c], B + (size_t)(kb + b_kk) * ldb + bcol);
            if (tid < 128) {
                int k = kb + a_kc;
                const float* src = (k < K0) ? (A0 + (size_t)a_r * K0 + k)
                                            : (A1 + (size_t)a_r * K1 + (k - K0));
                cp16(&As[pt][a_r][a_kc], src);
            }
        }
        CP_COMMIT();
    }

    for (int ct = 0; ct < ntiles; ct++) {
        CP_WAIT2();
        __syncthreads();
        const int st = ct & (SKS - 1);
        #pragma unroll
        for (int kk = 0; kk < 16; kk++) {
            float4 bv = *(const float4*)&Bs[st][kk][c4];
            float a0 = As[st][r0][kk];
            float a1 = As[st][r0 + 1][kk];
            acc[0][0] += a0 * bv.x; acc[0][1] += a0 * bv.y;
            acc[0][2] += a0 * bv.z; acc[0][3] += a0 * bv.w;
            acc[1][0] += a1 * bv.x; acc[1][1] += a1 * bv.y;
            acc[1][2] += a1 * bv.z; acc[1][3] += a1 * bv.w;
        }
        __syncthreads();
        int nt = ct + SKS - 1;
        if (nt < ntiles) {
            int kb = kstart + nt * 16;
            int st2 = nt & (SKS - 1);
            cp16(&Bs[st2][b_kk][b_c], B + (size_t)(kb + b_kk) * ldb + bcol);
            if (tid < 128) {
                int k = kb + a_kc;
                const float* src = (k < K0) ? (A0 + (size_t)a_r * K0 + k)
                                            : (A1 + (size_t)a_r * K1 + (k - K0));
                cp16(&As[st2][a_r][a_kc], src);
            }
        }
        CP_COMMIT();
    }

    float* po = part + ((size_t)blockIdx.y * 32 + r0) * Nout;
    #pragma unroll
    for (int j = 0; j < 4; j++) {
        int c = col0 + c4 + j;
        if (c < Nout) {
            po[c] = acc[0][j];
            po[Nout + c] = acc[1][j];
        }
    }
}

// ---------------- split-K reduce ----------------
__global__ void reduce_rows(const float* __restrict__ part, const float* __restrict__ bias,
                            float* __restrict__ out, int Nout, int nsplit, int relu) {
    int i = blockIdx.x * 256 + threadIdx.x;
    if (i >= 32 * Nout) return;
    int r = i / Nout, c = i - r * Nout;
    float s = bias[c];
    for (int k = 0; k < nsplit; k++) s += part[((size_t)k * 32 + r) * Nout + c];
    out[i] = relu ? fmaxf(s, 0.f) : s;
}

// ---------------- attention partial (K transposed, shuffle-free scores) ----
__global__ void attn_partial() {
    const int bh = blockIdx.x >> 3;
    const int chunk = blockIdx.x & 7;
    const int b = bh >> 3, h = bh & 7;
    const int tid = threadIdx.x;
    __shared__ float qs[64];
    __shared__ float sc[2][128];
    __shared__ float ev[128];
    __shared__ float red[4][64];

    if (tid < 64) {
        float q = buf_bqq[h * HD + tid];
        #pragma unroll
        for (int s = 0; s < 8; s++) q += buf_qpart[((size_t)s * 32 + b) * NE + h * HD + tid];
        qs[tid] = q;
    }
    __syncthreads();

    // scores: thread (n = tid&127, dh = tid>>7) sums half the d-range
    const int n = tid & 127, dh = tid >> 7;
    {
        const float* KT = buf_K + ((size_t)bh * HD + dh * 32) * NT + (chunk << 7) + n;
        float p = 0.f;
        #pragma unroll
        for (int d = 0; d < 32; d++)
            p += qs[dh * 32 + d] * KT[(size_t)d * NT];
        sc[dh][n] = p;
    }
    __syncthreads();

    float score = (sc[0][n] + sc[1][n]) * 0.125f;
    float m = blockReduceMax(score);
    float e = (dh == 0) ? expf(score - m) : 0.f;
    float s = blockReduceSum(e);
    if (dh == 0) ev[n] = expf(score - m);
    __syncthreads();

    // weighted V (unnormalized)
    const int d = tid & 63, grp = tid >> 6;
    const float* Vb = buf_V + (((size_t)bh << 10) + (chunk << 7)) * HD + d;
    float acc = 0.f;
    #pragma unroll 8
    for (int nn = grp * 32; nn < grp * 32 + 32; nn++)
        acc += ev[nn] * Vb[(size_t)nn * HD];
    red[grp][d] = acc;
    __syncthreads();
    if (tid < 64) {
        float v = red[0][tid] + red[1][tid] + red[2][tid] + red[3][tid];
        buf_pv[(size_t)blockIdx.x * HD + tid] = v;
        if (tid == 0) { buf_pm[blockIdx.x] = m; buf_ps[blockIdx.x] = s; }
    }
}

__global__ void attn_combine() {
    const int bh = blockIdx.x;
    const int b = bh >> 3, h = bh & 7;
    const int tid = threadIdx.x; // 64
    float M = -1e30f;
    #pragma unroll
    for (int c = 0; c < 8; c++) M = fmaxf(M, buf_pm[bh * 8 + c]);
    float T = 0.f, v = 0.f;
    #pragma unroll
    for (int c = 0; c < 8; c++) {
        float w = expf(buf_pm[bh * 8 + c] - M);
        T += buf_ps[bh * 8 + c] * w;
        v += buf_pv[(size_t)(bh * 8 + c) * HD + tid] * w;
    }
    buf_attn[b * NE + h * HD + tid] = v / T;
}

// ---------------- fused split-K reduce + GLU + double LN ----------------
__global__ void glu_ln_ln(const float* __restrict__ b_syn,
                          const float* __restrict__ g_syn, const float* __restrict__ be_syn,
                          const float* __restrict__ g_pm, const float* __restrict__ be_pm) {
    int b = blockIdx.x, tid = threadIdx.x;
    float v[8];
    #pragma unroll
    for (int j = 0; j < 8; j++) {
        int d = tid + j * 256;
        float a = b_syn[d], gg = b_syn[ND + d];
        #pragma unroll
        for (int s = 0; s < 8; s++) {
            const float* hp = buf_hpart + ((size_t)s * 32 + b) * (2 * ND);
            a += hp[d];
            gg += hp[ND + d];
        }
        v[j] = a * (1.f / (1.f + expf(-gg)));
    }
    float s = 0.f;
    #pragma unroll
    for (int j = 0; j < 8; j++) s += v[j];
    s = blockReduceSum(s);
    float m = s / ND;
    float var = 0.f;
    #pragma unroll
    for (int j = 0; j < 8; j++) { float d = v[j] - m; var += d * d; }
    var = blockReduceSum(var);
    float inv = rsqrtf(var / ND + 1e-5f);
    #pragma unroll
    for (int j = 0; j < 8; j++) {
        int d = tid + j * 256;
        v[j] = (v[j] - m) * inv * g_syn[d] + be_syn[d];
    }
    s = 0.f;
    #pragma unroll
    for (int j = 0; j < 8; j++) s += v[j];
    s = blockReduceSum(s);
    float m2 = s / ND;
    var = 0.f;
    #pragma unroll
    for (int j = 0; j < 8; j++) { float d = v[j] - m2; var += d * d; }
    var = blockReduceSum(var);
    float inv2 = rsqrtf(var / ND + 1e-5f);
    #pragma unroll
    for (int j = 0; j < 8; j++) {
        int d = tid + j * 256;
        buf_hpm[(size_t)b * ND + d] = (v[j] - m2) * inv2 * g_pm[d] + be_pm[d];
    }
}

// ---------------- fused pred reduce + entropy + writes ----------------
__global__ void entropy_write(const float* __restrict__ b_out, float* __restrict__ dout, int t) {
    int b = blockIdx.x, tid = threadIdx.x;
    __shared__ float sp[NOUT];
    for (int i = tid; i < NOUT; i += 256)
        sp[i] = b_out[i] + buf_predpart[(size_t)b * NOUT + i]
                         + buf_predpart[((size_t)32 + b) * NOUT + i];
    __syncthreads();
    float m = -1e30f;
    for (int i = tid; i < NOUT; i += 256) m = fmaxf(m, sp[i]);
    m = blockReduceMax(m);
    float s = 0.f;
    for (int i = tid; i < NOUT; i += 256) s += expf(sp[i] - m);
    s = blockReduceSum(s);
    float lse = m + logf(s);
    float ent = 0.f;
    for (int i = tid; i < NOUT; i += 256) {
        float pv = sp[i];
        float lp = pv - lse;
        ent += expf(lp) * lp;
        dout[(size_t)b * NOUT * NSTEP + (size_t)i * NSTEP + t] = pv;
    }
    ent = blockReduceSum(ent);
    if (tid == 0) {
        float ne = -ent / logf((float)NOUT);
        dout[CERT_BASE + b * (2 * NSTEP) + t] = ne;
        dout[CERT_BASE + b * (2 * NSTEP) + NSTEP + t] = 1.f - ne;
    }
}

// ---------------- launch ----------------
extern "C" void kernel_launch(void* const* d_in, const int* in_sizes, int n_in,
                              void* d_out, int out_size) {
    const float* x     = (const float*)d_in[0];
    const float* W_kv  = (const float*)d_in[1];
    const float* b_kv  = (const float*)d_in[2];
    const float* g_kv  = (const float*)d_in[3];
    const float* be_kv = (const float*)d_in[4];
    const float* W_q   = (const float*)d_in[5];
    const float* b_q   = (const float*)d_in[6];
    const float* W_in  = (const float*)d_in[7];
    const float* b_in  = (const float*)d_in[8];
    const float* W_ao  = (const float*)d_in[9];
    const float* b_ao  = (const float*)d_in[10];
    const float* W_syn = (const float*)d_in[11];
    const float* b_syn = (const float*)d_in[12];
    const float* g_syn = (const float*)d_in[13];
    const float* be_syn= (const float*)d_in[14];
    const float* g_pm  = (const float*)d_in[15];
    const float* be_pm = (const float*)d_in[16];
    const float* W1    = (const float*)d_in[17];
    const float* b1    = (const float*)d_in[18];
    const float* W2    = (const float*)d_in[19];
    const float* b2    = (const float*)d_in[20];
    const float* start = (const float*)d_in[21];
    const float* dec_a = (const float*)d_in[22];
    const float* dec_o = (const float*)d_in[23];
    const float* W_out = (const float*)d_in[24];
    const float* b_out = (const float*)d_in[25];
    const int*   idx_a = (const int*)d_in[26];
    const int*   idx_o = (const int*)d_in[27];
    float* out = (float*)d_out;

    float *p_feats, *p_kv, *p_K, *p_V, *p_Wqq;
    float *p_syncA, *p_attn, *p_attno, *p_act, *p_hpm, *p_t1, *p_syncO;
    float *p_qpart, *p_attnopart, *p_hpart, *p_w1part, *p_w2part, *p_predpart;
    cudaGetSymbolAddress((void**)&p_feats, buf_feats);
    cudaGetSymbolAddress((void**)&p_kv,    buf_kv);
    cudaGetSymbolAddress((void**)&p_K,     buf_K);
    cudaGetSymbolAddress((void**)&p_V,     buf_V);
    cudaGetSymbolAddress((void**)&p_Wqq,   buf_Wqq);
    cudaGetSymbolAddress((void**)&p_syncA, buf_syncA);
    cudaGetSymbolAddress((void**)&p_attn,  buf_attn);
    cudaGetSymbolAddress((void**)&p_attno, buf_attno);
    cudaGetSymbolAddress((void**)&p_act,   buf_act);
    cudaGetSymbolAddress((void**)&p_hpm,   buf_hpm);
    cudaGetSymbolAddress((void**)&p_t1,    buf_t1);
    cudaGetSymbolAddress((void**)&p_syncO, buf_syncO);
    cudaGetSymbolAddress((void**)&p_qpart,    buf_qpart);
    cudaGetSymbolAddress((void**)&p_attnopart, buf_attnopart);
    cudaGetSymbolAddress((void**)&p_hpart,    buf_hpart);
    cudaGetSymbolAddress((void**)&p_w1part,   buf_w1part);
    cudaGetSymbolAddress((void**)&p_w2part,   buf_w2part);
    cudaGetSymbolAddress((void**)&p_predpart, buf_predpart);

    // ---- precompute ----
    transpose_x<<<dim3(NT / 32, NC / 32, NB), dim3(32, 8)>>>(x);
    gemm_tf32<<<dim3(NE / 64, (NB * NT) / 128), 256>>>(p_feats, NC, W_kv, NE, b_kv, p_kv, NE, NC, 0);
    ln_rows<<<NB * NT, 256>>>(p_kv, NE, g_kv, be_kv);
    gemm_tf32<<<dim3(NE / 64, (NB * NT) / 128), 256>>>(p_kv, NE, W_in + NE,     3 * NE, b_in + NE,     p_K, NE, NE, 1);
    gemm_tf32<<<dim3(NE / 64, (NB * NT) / 128), 256>>>(p_kv, NE, W_in + 2 * NE, 3 * NE, b_in + 2 * NE, p_V, NE, NE, 2);
    gemm_tf32<<<dim3(NE / 64, NE / 128), 256>>>(W_q, NE, W_in, 3 * NE, (const float*)0, p_Wqq, NE, NE, 0);
    make_bqq<<<2, 256>>>(b_q, W_in, b_in);
    init_state<<<(NB * ND + 255) / 256, 256>>>(start);

    // ---- recurrent loop ----
    for (int t = 0; t < NSTEP; t++) {
        syncA_update<<<NB, NA_>>>(idx_a, dec_a);
        skinny_gemm<<<dim3(NE / 64, 8), 256>>>(p_syncA, NA_, (const float*)0, 0,
                                               p_Wqq, NE, p_qpart, NE, NA_ / 8);
        attn_partial<<<NB * NH * 8, 256>>>();
        attn_combine<<<NB * NH, 64>>>();
        skinny_gemm<<<dim3(NE / 64, 4), 256>>>(p_attn, NE, (const float*)0, 0,
                                               W_ao, NE, p_attnopart, NE, NE / 4);
        reduce_rows<<<(32 * NE + 255) / 256, 256>>>(p_attnopart, b_ao, p_attno, NE, 4, 0);
        skinny_gemm<<<dim3((2 * ND) / 64, 8), 256>>>(p_attno, NE, p_act, ND,
                                                     W_syn, 2 * ND, p_hpart, 2 * ND, (NE + ND) / 8);
        glu_ln_ln<<<NB, 256>>>(b_syn, g_syn, be_syn, g_pm, be_pm);
        skinny_gemm<<<dim3(ND / 64, 4), 256>>>(p_hpm, ND, (const float*)0, 0,
                                               W1, ND, p_w1part, ND, ND / 4);
        reduce_rows<<<(32 * ND + 255) / 256, 256>>>(p_w1part, b1, p_t1, ND, 4, 1);
        skinny_gemm<<<dim3(ND / 64, 4), 256>>>(p_t1, ND, (const float*)0, 0,
                                               W2, ND, p_w2part, ND, ND / 4);
        reduce_rows<<<(32 * ND + 255) / 256, 256>>>(p_w2part, b2, p_act, ND, 4, 1);
        syncO_update<<<NB, NO_>>>(idx_o, dec_o, out, t);
        skinny_gemm<<<dim3((NOUT + 63) / 64, 2), 256>>>(p_syncO, NO_, (const float*)0, 0,
                                                        W_out, NOUT, p_predpart, NOUT, NO_ / 2);
        entropy_write<<<NB, 256>>>(b_out, out, t);
    }
}